// round 8
// baseline (speedup 1.0000x reference)
#include <cuda_runtime.h>
#include <cuda_bf16.h>
#include <math.h>
#include <stdint.h>

#define B_    256
#define C_    3
#define IMG_  32
#define D_    256
#define H_    8
#define HD_   32
#define T1_   65
#define MLPH_ 2048
#define HEADH_ 8192
#define NCLS_ 10
#define PDIM_ 48
#define ND_   (T1_*D_)   // 16640
#define SPLITK 4
#define KCHUNK (ND_/SPLITK)   // 4160

// ---------------- scratch ----------------------------------------------------
__device__ float g_out[B_*T1_*D_];
__device__ float g_h[B_*T1_*D_];
__device__ float g_qkv[B_*T1_*3*D_];
__device__ float g_m[B_*T1_*MLPH_];
__device__ float g_hid[B_*HEADH_];
__device__ float g_part[SPLITK*B_*HEADH_];

// ---------------- patch embed + cls + positional encoding --------------------
__global__ void patch_embed_kernel(const float* __restrict__ x,
                                   const float* __restrict__ cls,
                                   const float* __restrict__ Wp,
                                   const float* __restrict__ bp,
                                   float* __restrict__ out) {
    int b = blockIdx.x;
    int t = blockIdx.y;
    int d = threadIdx.x;
    int i = d >> 1;
    float div = expf(-(float)(2 * i) * (9.210340371976184f / 256.0f));
    float ang = (float)t * div;
    float pe = (d & 1) ? cosf(ang) : sinf(ang);

    if (t == 0) {
        out[(b * T1_) * D_ + d] = cls[d] + pe;
    } else {
        __shared__ float sp[PDIM_];
        int tt = t - 1;
        int ni = tt >> 3, nj = tt & 7;
        if (d < PDIM_) {
            int c  = d / 16;
            int pi = (d >> 2) & 3;
            int pj = d & 3;
            sp[d] = x[((b * C_ + c) * IMG_ + ni * 4 + pi) * IMG_ + nj * 4 + pj];
        }
        __syncthreads();
        float acc = bp[d];
        #pragma unroll
        for (int k = 0; k < PDIM_; k++) acc += sp[k] * Wp[k * D_ + d];
        out[((b * T1_) + t) * D_ + d] = acc + pe;
    }
}

// ---------------- LayerNorm over whole (T1,D) slab per sample ----------------
__global__ void ln2d_kernel(const float* __restrict__ X,
                            const float* __restrict__ w,
                            const float* __restrict__ bb,
                            float* __restrict__ Y) {
    int b = blockIdx.x;
    const float* xb = X + b * ND_;
    float s = 0.f, s2 = 0.f;
    for (int i = threadIdx.x; i < ND_; i += 256) {
        float v = xb[i];
        s += v; s2 += v * v;
    }
    __shared__ float rs[8], rs2[8], bc[2];
    #pragma unroll
    for (int o = 16; o > 0; o >>= 1) {
        s  += __shfl_down_sync(0xffffffffu, s,  o);
        s2 += __shfl_down_sync(0xffffffffu, s2, o);
    }
    int wid = threadIdx.x >> 5, lid = threadIdx.x & 31;
    if (lid == 0) { rs[wid] = s; rs2[wid] = s2; }
    __syncthreads();
    if (threadIdx.x == 0) {
        float ts = 0.f, ts2 = 0.f;
        #pragma unroll
        for (int k = 0; k < 8; k++) { ts += rs[k]; ts2 += rs2[k]; }
        float mu  = ts / (float)ND_;
        float var = ts2 / (float)ND_ - mu * mu;
        bc[0] = mu;
        bc[1] = rsqrtf(var + 1e-5f);
    }
    __syncthreads();
    float mu = bc[0], rsg = bc[1];
    float* yb = Y + b * ND_;
    for (int i = threadIdx.x; i < ND_; i += 256) {
        yb[i] = (xb[i] - mu) * rsg * w[i] + bb[i];
    }
}

// ---------------- bf16-split tensor-core GEMM (mma.sync m16n8k16) ------------
// C(M,N) = act(A(M,K) @ W(K,N) + bias) (+R). fp32 = bf16_hi + bf16_lo,
// C ~= AhWh + AhWl + AlWh, fp32 accumulate.
// Tile 128x128, BK=32, 8 warps, warp tile 64x32.
// ACT: 0 none, 1 relu, 2 silu, 3 raw partial (no bias/act; split-K z-offset out)
#define PITCH 40
#define REG_A 0
#define REG_AL 10240
#define REG_BH 20480
#define REG_BL 30720
#define BUFSZ 40960
#define GSMEM_TOTAL (2*BUFSZ)

__device__ __forceinline__ void mma16816(float* c, const uint32_t* a, const uint32_t* b) {
    asm volatile(
        "mma.sync.aligned.m16n8k16.row.col.f32.bf16.bf16.f32 "
        "{%0,%1,%2,%3}, {%4,%5,%6,%7}, {%8,%9}, {%0,%1,%2,%3};"
        : "+f"(c[0]), "+f"(c[1]), "+f"(c[2]), "+f"(c[3])
        : "r"(a[0]), "r"(a[1]), "r"(a[2]), "r"(a[3]), "r"(b[0]), "r"(b[1]));
}
__device__ __forceinline__ void split_pair(float x, float y,
                                           __nv_bfloat162& hi, __nv_bfloat162& lo) {
    hi = __float22bfloat162_rn(make_float2(x, y));
    float2 hf = __bfloat1622float2(hi);
    lo = __float22bfloat162_rn(make_float2(x - hf.x, y - hf.y));
}

template<int ACT, bool RES>
__global__ void __launch_bounds__(256) gemm_tc(
    const float* __restrict__ A, const float* __restrict__ W,
    const float* __restrict__ bias, const float* __restrict__ R,
    float* __restrict__ Cc, int M, int N, int K, int kChunk)
{
    extern __shared__ char smem[];
    const int tid = threadIdx.x;
    const int wid = tid >> 5;
    const int lane = tid & 31;
    const int wm = wid >> 2, wn = wid & 3;
    const int m0 = blockIdx.y * 128, n0 = blockIdx.x * 128;
    const int kbase = blockIdx.z * kChunk;
    float* Cz = Cc + (long)blockIdx.z * M * N;
    const int gid = lane >> 2, tig = lane & 3;

    const int bn = tid & 127;
    const int bkh = (tid >> 7) * 16;

    float c[4][4][4];
    #pragma unroll
    for (int i = 0; i < 4; i++)
        #pragma unroll
        for (int j = 0; j < 4; j++)
            #pragma unroll
            for (int r = 0; r < 4; r++) c[i][j][r] = 0.f;

    const int nk = kChunk / 32;
    float4 ra[4];
    float rb[16];

    auto ldg_tile = [&](int t) {
        #pragma unroll
        for (int i = 0; i < 4; i++) {
            int lin = tid + i * 256;
            int row = lin >> 3, q = lin & 7;
            ra[i] = *(const float4*)&A[(long)(m0 + row) * K + kbase + t * 32 + q * 4];
        }
        const float* Wb = W + (long)(kbase + t * 32 + bkh) * N + n0 + bn;
        #pragma unroll
        for (int p = 0; p < 16; p++) rb[p] = Wb[(long)p * N];
    };
    auto sts_tile = [&](int buf) {
        char* base = smem + buf * BUFSZ;
        #pragma unroll
        for (int i = 0; i < 4; i++) {
            int lin = tid + i * 256;
            int row = lin >> 3, q = lin & 7;
            __nv_bfloat162 h0, l0, h1, l1;
            split_pair(ra[i].x, ra[i].y, h0, l0);
            split_pair(ra[i].z, ra[i].w, h1, l1);
            int e = row * PITCH + q * 4;
            *(__nv_bfloat162*)(base + REG_A  + e * 2)     = h0;
            *(__nv_bfloat162*)(base + REG_A  + e * 2 + 4) = h1;
            *(__nv_bfloat162*)(base + REG_AL + e * 2)     = l0;
            *(__nv_bfloat162*)(base + REG_AL + e * 2 + 4) = l1;
        }
        #pragma unroll
        for (int p = 0; p < 8; p++) {
            __nv_bfloat162 h, l;
            split_pair(rb[2 * p], rb[2 * p + 1], h, l);
            int e = bn * PITCH + bkh + 2 * p;
            *(__nv_bfloat162*)(base + REG_BH + e * 2) = h;
            *(__nv_bfloat162*)(base + REG_BL + e * 2) = l;
        }
    };

    ldg_tile(0);
    sts_tile(0);
    __syncthreads();

    for (int t = 0; t < nk; t++) {
        const int buf = t & 1;
        if (t + 1 < nk) ldg_tile(t + 1);

        const char* ahp = smem + buf * BUFSZ + REG_A;
        const char* alp = smem + buf * BUFSZ + REG_AL;
        const char* bhp = smem + buf * BUFSZ + REG_BH;
        const char* blp = smem + buf * BUFSZ + REG_BL;

        #pragma unroll
        for (int ks = 0; ks < 2; ks++) {
            uint32_t ah[4][4], al[4][4], bh[4][2], bl[4][2];
            const int acol = ks * 16 + tig * 2;
            #pragma unroll
            for (int am = 0; am < 4; am++) {
                const int arow = wm * 64 + am * 16 + gid;
                const int e00 = (arow * PITCH + acol) * 2;
                const int e10 = ((arow + 8) * PITCH + acol) * 2;
                ah[am][0] = *(const uint32_t*)(ahp + e00);
                ah[am][1] = *(const uint32_t*)(ahp + e10);
                ah[am][2] = *(const uint32_t*)(ahp + e00 + 16);
                ah[am][3] = *(const uint32_t*)(ahp + e10 + 16);
                al[am][0] = *(const uint32_t*)(alp + e00);
                al[am][1] = *(const uint32_t*)(alp + e10);
                al[am][2] = *(const uint32_t*)(alp + e00 + 16);
                al[am][3] = *(const uint32_t*)(alp + e10 + 16);
            }
            #pragma unroll
            for (int an = 0; an < 4; an++) {
                const int brow = wn * 32 + an * 8 + gid;
                const int e = (brow * PITCH + acol) * 2;
                bh[an][0] = *(const uint32_t*)(bhp + e);
                bh[an][1] = *(const uint32_t*)(bhp + e + 16);
                bl[an][0] = *(const uint32_t*)(blp + e);
                bl[an][1] = *(const uint32_t*)(blp + e + 16);
            }
            #pragma unroll
            for (int am = 0; am < 4; am++)
                #pragma unroll
                for (int an = 0; an < 4; an++) {
                    mma16816(c[am][an], ah[am], bh[an]);
                    mma16816(c[am][an], ah[am], bl[an]);
                    mma16816(c[am][an], al[am], bh[an]);
                }
        }

        if (t + 1 < nk) sts_tile(buf ^ 1);
        __syncthreads();
    }

    // ---- epilogue ----
    #pragma unroll
    for (int am = 0; am < 4; am++) {
        #pragma unroll
        for (int an = 0; an < 4; an++) {
            const int col = n0 + wn * 32 + an * 8 + tig * 2;
            float bx = 0.f, by = 0.f;
            if (ACT != 3) { bx = bias[col]; by = bias[col + 1]; }
            #pragma unroll
            for (int hrow = 0; hrow < 2; hrow++) {
                const int m = m0 + wm * 64 + am * 16 + gid + hrow * 8;
                float vx = c[am][an][hrow * 2 + 0] + bx;
                float vy = c[am][an][hrow * 2 + 1] + by;
                if (ACT == 1) { vx = fmaxf(vx, 0.f); vy = fmaxf(vy, 0.f); }
                if (ACT == 2) {
                    vx = vx / (1.f + expf(-vx));
                    vy = vy / (1.f + expf(-vy));
                }
                if (RES) {
                    const float2 r2 = *(const float2*)&R[(long)m * N + col];
                    vx += r2.x; vy += r2.y;
                }
                *(float2*)&Cz[(long)m * N + col] = make_float2(vx, vy);
            }
        }
    }
}

// ---------------- split-K reduce + bias + silu --------------------------------
__global__ void reduce_silu_kernel(const float* __restrict__ part,
                                   const float* __restrict__ bias,
                                   float* __restrict__ out) {
    const long MN = (long)B_ * HEADH_;
    const long i4 = (long)blockIdx.x * 256 + threadIdx.x;   // float4 index
    const long e = i4 * 4;
    const int n = (int)(e % HEADH_);
    float4 a = *(const float4*)&part[e];
    #pragma unroll
    for (int z = 1; z < SPLITK; z++) {
        const float4 p = *(const float4*)&part[z * MN + e];
        a.x += p.x; a.y += p.y; a.z += p.z; a.w += p.w;
    }
    const float4 bi = *(const float4*)&bias[n];
    a.x += bi.x; a.y += bi.y; a.z += bi.z; a.w += bi.w;
    a.x = a.x / (1.f + expf(-a.x));
    a.y = a.y / (1.f + expf(-a.y));
    a.z = a.z / (1.f + expf(-a.z));
    a.w = a.w / (1.f + expf(-a.w));
    *(float4*)&out[e] = a;
}

// ---------------- fused attention: warp-per-row, lane-parallel ---------------
__global__ __launch_bounds__(256)
void attn_kernel(const float* __restrict__ qkv, float* __restrict__ out) {
    const int h = blockIdx.x, b = blockIdx.y;
    __shared__ float Kt[32 * 67];      // [d][k] transposed, pitch 67
    __shared__ float Vs[T1_ * 32];     // [k][d]
    __shared__ float P[8 * 68];        // per-warp softmax probs
    const float* base = qkv + (long)b * T1_ * 768 + h * 96;
    const int tid = threadIdx.x;
    const int w = tid >> 5, lane = tid & 31;

    for (int idx = tid; idx < T1_ * 32; idx += 256) {
        int k = idx >> 5, d = idx & 31;
        Kt[d * 67 + k] = base[k * 768 + 32 + d];
        Vs[k * 32 + d] = base[k * 768 + 64 + d];
    }
    __syncthreads();

    for (int r = w; r < T1_; r += 8) {
        const float ql = base[r * 768 + lane];
        float s0 = 0.f, s1 = 0.f, s2 = 0.f;
        #pragma unroll
        for (int d = 0; d < 32; d++) {
            const float qd = __shfl_sync(0xffffffffu, ql, d);
            s0 += qd * Kt[d * 67 + lane];
            s1 += qd * Kt[d * 67 + lane + 32];
            float kv2 = 0.f;
            if (lane == 0) kv2 = Kt[d * 67 + 64];
            s2 += qd * kv2;
        }
        const float sc = 0.17677669529663687f;
        s0 *= sc; s1 *= sc; s2 *= sc;

        float mloc = fmaxf(s0, s1);
        if (lane == 0) mloc = fmaxf(mloc, s2);
        #pragma unroll
        for (int o = 16; o > 0; o >>= 1)
            mloc = fmaxf(mloc, __shfl_xor_sync(0xffffffffu, mloc, o));

        const float e0 = expf(s0 - mloc);
        const float e1 = expf(s1 - mloc);
        const float e2 = (lane == 0) ? expf(s2 - mloc) : 0.f;
        float sl = e0 + e1 + e2;
        #pragma unroll
        for (int o = 16; o > 0; o >>= 1)
            sl += __shfl_xor_sync(0xffffffffu, sl, o);
        const float inv = 1.f / sl;

        P[w * 68 + lane]      = e0 * inv;
        P[w * 68 + 32 + lane] = e1 * inv;
        if (lane == 0) P[w * 68 + 64] = e2 * inv;
        __syncwarp();

        float acc = 0.f;
        #pragma unroll 5
        for (int k = 0; k < T1_; k++)
            acc += P[w * 68 + k] * Vs[k * 32 + lane];

        out[((long)b * T1_ + r) * D_ + h * HD_ + lane] += acc;
        __syncwarp();
    }
}

// ---------------- final classifier head --------------------------------------
__global__ void head2_kernel(const float* __restrict__ hid, const float* __restrict__ W2,
                             const float* __restrict__ b2, float* __restrict__ out) {
    int b = blockIdx.x;
    float acc[NCLS_] = {};
    for (int k = threadIdx.x; k < HEADH_; k += 256) {
        float hv = hid[(long)b * HEADH_ + k];
        #pragma unroll
        for (int c = 0; c < NCLS_; c++) acc[c] += hv * W2[k * NCLS_ + c];
    }
    __shared__ float red[256];
    for (int c = 0; c < NCLS_; c++) {
        red[threadIdx.x] = acc[c];
        __syncthreads();
        for (int o = 128; o > 0; o >>= 1) {
            if (threadIdx.x < o) red[threadIdx.x] += red[threadIdx.x + o];
            __syncthreads();
        }
        if (threadIdx.x == 0) out[b * NCLS_ + c] = red[0] + b2[c];
        __syncthreads();
    }
}

// -----------------------------------------------------------------------------
extern "C" void kernel_launch(void* const* d_in, const int* in_sizes, int n_in,
                              void* d_out, int out_size) {
    const float* x      = (const float*)d_in[0];
    const float* cls    = (const float*)d_in[1];
    const float* Wp     = (const float*)d_in[2];
    const float* bp     = (const float*)d_in[3];
    const float* qkv_w  = (const float*)d_in[4];
    const float* qkv_b  = (const float*)d_in[5];
    const float* ln_w   = (const float*)d_in[6];
    const float* ln_b   = (const float*)d_in[7];
    const float* mlp1_w = (const float*)d_in[8];
    const float* mlp1_b = (const float*)d_in[9];
    const float* mlp2_w = (const float*)d_in[10];
    const float* mlp2_b = (const float*)d_in[11];
    const float* h1w    = (const float*)d_in[12];
    const float* h1b    = (const float*)d_in[13];
    const float* h2w    = (const float*)d_in[14];
    const float* h2b    = (const float*)d_in[15];
    float* out = (float*)d_out;

    float *p_out, *p_h, *p_qkv, *p_m, *p_hid, *p_part;
    cudaGetSymbolAddress((void**)&p_out, g_out);
    cudaGetSymbolAddress((void**)&p_h,   g_h);
    cudaGetSymbolAddress((void**)&p_qkv, g_qkv);
    cudaGetSymbolAddress((void**)&p_m,   g_m);
    cudaGetSymbolAddress((void**)&p_hid, g_hid);
    cudaGetSymbolAddress((void**)&p_part, g_part);

    cudaFuncSetAttribute(gemm_tc<0,false>, cudaFuncAttributeMaxDynamicSharedMemorySize, GSMEM_TOTAL);
    cudaFuncSetAttribute(gemm_tc<1,false>, cudaFuncAttributeMaxDynamicSharedMemorySize, GSMEM_TOTAL);
    cudaFuncSetAttribute(gemm_tc<0,true>,  cudaFuncAttributeMaxDynamicSharedMemorySize, GSMEM_TOTAL);
    cudaFuncSetAttribute(gemm_tc<3,false>, cudaFuncAttributeMaxDynamicSharedMemorySize, GSMEM_TOTAL);

    dim3 gPatch(B_, T1_);
    patch_embed_kernel<<<gPatch, 256>>>(x, cls, Wp, bp, p_out);

    const int Mt = B_ * T1_;   // 16640
    for (int l = 0; l < 2; l++) {
        ln2d_kernel<<<B_, 256>>>(p_out, ln_w + l * ND_, ln_b + l * ND_, p_h);
        gemm_tc<0, false><<<dim3(768 / 128, Mt / 128), 256, GSMEM_TOTAL>>>(
            p_h, qkv_w + l * D_ * 768, qkv_b + l * 768, nullptr, p_qkv,
            Mt, 768, D_, D_);
        attn_kernel<<<dim3(H_, B_), 256>>>(p_qkv, p_out);
        ln2d_kernel<<<B_, 256>>>(p_out, ln_w + l * ND_, ln_b + l * ND_, p_h);
        gemm_tc<1, false><<<dim3(MLPH_ / 128, Mt / 128), 256, GSMEM_TOTAL>>>(
            p_h, mlp1_w + l * D_ * MLPH_, mlp1_b + l * MLPH_, nullptr, p_m,
            Mt, MLPH_, D_, D_);
        gemm_tc<0, true><<<dim3(D_ / 128, Mt / 128), 256, GSMEM_TOTAL>>>(
            p_m, mlp2_w + l * MLPH_ * D_, mlp2_b + l * D_, p_out, p_out,
            Mt, D_, MLPH_, MLPH_);
    }

    // head1 split-K: partials then fused reduce+bias+silu
    gemm_tc<3, false><<<dim3(HEADH_ / 128, B_ / 128, SPLITK), 256, GSMEM_TOTAL>>>(
        p_out, h1w, h1b, nullptr, p_part, B_, HEADH_, ND_, KCHUNK);
    reduce_silu_kernel<<<(B_ * HEADH_) / 1024, 256>>>(p_part, h1b, p_hid);

    head2_kernel<<<B_, 256>>>(p_hid, h2w, h2b, out);
}

// round 9
// speedup vs baseline: 1.1245x; 1.1245x over previous
#include <cuda_runtime.h>
#include <cuda_bf16.h>
#include <math.h>
#include <stdint.h>

#define B_    256
#define C_    3
#define IMG_  32
#define D_    256
#define H_    8
#define HD_   32
#define T1_   65
#define MLPH_ 2048
#define HEADH_ 8192
#define NCLS_ 10
#define PDIM_ 48
#define ND_   (T1_*D_)   // 16640
#define SPLITK 4
#define KCHUNK (ND_/SPLITK)   // 4160

// ---------------- scratch ----------------------------------------------------
__device__ float g_out[B_*T1_*D_];
__device__ float g_h[B_*T1_*D_];
__device__ float g_qkv[B_*T1_*3*D_];
__device__ float g_m[B_*T1_*MLPH_];
__device__ float g_hid[B_*HEADH_];
__device__ float g_part[SPLITK*B_*HEADH_];

// ---------------- patch embed + cls + positional encoding --------------------
__global__ void patch_embed_kernel(const float* __restrict__ x,
                                   const float* __restrict__ cls,
                                   const float* __restrict__ Wp,
                                   const float* __restrict__ bp,
                                   float* __restrict__ out) {
    int b = blockIdx.x;
    int t = blockIdx.y;
    int d = threadIdx.x;
    int i = d >> 1;
    float div = expf(-(float)(2 * i) * (9.210340371976184f / 256.0f));
    float ang = (float)t * div;
    float pe = (d & 1) ? cosf(ang) : sinf(ang);

    if (t == 0) {
        out[(b * T1_) * D_ + d] = cls[d] + pe;
    } else {
        __shared__ float sp[PDIM_];
        int tt = t - 1;
        int ni = tt >> 3, nj = tt & 7;
        if (d < PDIM_) {
            int c  = d / 16;
            int pi = (d >> 2) & 3;
            int pj = d & 3;
            sp[d] = x[((b * C_ + c) * IMG_ + ni * 4 + pi) * IMG_ + nj * 4 + pj];
        }
        __syncthreads();
        float acc = bp[d];
        #pragma unroll
        for (int k = 0; k < PDIM_; k++) acc += sp[k] * Wp[k * D_ + d];
        out[((b * T1_) + t) * D_ + d] = acc + pe;
    }
}

// ---------------- LayerNorm over whole (T1,D) slab per sample ----------------
__global__ void ln2d_kernel(const float* __restrict__ X,
                            const float* __restrict__ w,
                            const float* __restrict__ bb,
                            float* __restrict__ Y) {
    int b = blockIdx.x;
    const float* xb = X + b * ND_;
    float s = 0.f, s2 = 0.f;
    for (int i = threadIdx.x; i < ND_; i += 256) {
        float v = xb[i];
        s += v; s2 += v * v;
    }
    __shared__ float rs[8], rs2[8], bc[2];
    #pragma unroll
    for (int o = 16; o > 0; o >>= 1) {
        s  += __shfl_down_sync(0xffffffffu, s,  o);
        s2 += __shfl_down_sync(0xffffffffu, s2, o);
    }
    int wid = threadIdx.x >> 5, lid = threadIdx.x & 31;
    if (lid == 0) { rs[wid] = s; rs2[wid] = s2; }
    __syncthreads();
    if (threadIdx.x == 0) {
        float ts = 0.f, ts2 = 0.f;
        #pragma unroll
        for (int k = 0; k < 8; k++) { ts += rs[k]; ts2 += rs2[k]; }
        float mu  = ts / (float)ND_;
        float var = ts2 / (float)ND_ - mu * mu;
        bc[0] = mu;
        bc[1] = rsqrtf(var + 1e-5f);
    }
    __syncthreads();
    float mu = bc[0], rsg = bc[1];
    float* yb = Y + b * ND_;
    for (int i = threadIdx.x; i < ND_; i += 256) {
        yb[i] = (xb[i] - mu) * rsg * w[i] + bb[i];
    }
}

// ---------------- bf16-split tensor-core GEMM (mma.sync m16n8k16) ------------
// C(M,N) = act(A(M,K) @ W(K,N) + bias) (+R). fp32 = bf16_hi + bf16_lo,
// C ~= AhWh + AhWl + AlWh, fp32 accumulate.
// CTA tile 256x128, BK=32, 512 threads (16 warps, 4/SMSP), warp tile 64x32.
// ACT: 0 none, 1 relu, 2 silu, 3 raw partial (split-K, z-offset output)
#define PITCH 40
#define SA_H 0
#define SA_L 20480
#define SB_H 40960
#define SB_L 51200
#define BUFSZ 61440
#define GSMEM_TOTAL (2*BUFSZ)

__device__ __forceinline__ void mma16816(float* c, const uint32_t* a, const uint32_t* b) {
    asm volatile(
        "mma.sync.aligned.m16n8k16.row.col.f32.bf16.bf16.f32 "
        "{%0,%1,%2,%3}, {%4,%5,%6,%7}, {%8,%9}, {%0,%1,%2,%3};"
        : "+f"(c[0]), "+f"(c[1]), "+f"(c[2]), "+f"(c[3])
        : "r"(a[0]), "r"(a[1]), "r"(a[2]), "r"(a[3]), "r"(b[0]), "r"(b[1]));
}
__device__ __forceinline__ void split_pair(float x, float y,
                                           __nv_bfloat162& hi, __nv_bfloat162& lo) {
    hi = __float22bfloat162_rn(make_float2(x, y));
    float2 hf = __bfloat1622float2(hi);
    lo = __float22bfloat162_rn(make_float2(x - hf.x, y - hf.y));
}

template<int ACT, bool RES>
__global__ void __launch_bounds__(512, 1) gemm_tc(
    const float* __restrict__ A, const float* __restrict__ W,
    const float* __restrict__ bias, const float* __restrict__ R,
    float* __restrict__ Cc, int M, int N, int K, int kChunk)
{
    extern __shared__ char smem[];
    const int tid = threadIdx.x;
    const int wid = tid >> 5;
    const int lane = tid & 31;
    const int wm = wid >> 2, wn = wid & 3;       // 4x4 warps -> 64x32 tiles
    const int m0 = blockIdx.y * 256, n0 = blockIdx.x * 128;
    const int kbase = blockIdx.z * kChunk;
    float* Cz = Cc + (long)blockIdx.z * M * N;
    const int gid = lane >> 2, tig = lane & 3;

    const int bn = tid & 127;
    const int bkh = (tid >> 7) * 8;              // 4 groups x 8 k-values

    float c[4][4][4];
    #pragma unroll
    for (int i = 0; i < 4; i++)
        #pragma unroll
        for (int j = 0; j < 4; j++)
            #pragma unroll
            for (int r = 0; r < 4; r++) c[i][j][r] = 0.f;

    const int nk = kChunk / 32;
    float4 ra[4];
    float rb[8];

    auto ldg_tile = [&](int t) {
        #pragma unroll
        for (int i = 0; i < 4; i++) {
            int lin = tid + i * 512;
            int row = lin >> 3, q = lin & 7;
            ra[i] = *(const float4*)&A[(long)(m0 + row) * K + kbase + t * 32 + q * 4];
        }
        const float* Wb = W + (long)(kbase + t * 32 + bkh) * N + n0 + bn;
        #pragma unroll
        for (int p = 0; p < 8; p++) rb[p] = Wb[(long)p * N];
    };
    auto sts_tile = [&](int buf) {
        char* base = smem + buf * BUFSZ;
        #pragma unroll
        for (int i = 0; i < 4; i++) {
            int lin = tid + i * 512;
            int row = lin >> 3, q = lin & 7;
            __nv_bfloat162 h0, l0, h1, l1;
            split_pair(ra[i].x, ra[i].y, h0, l0);
            split_pair(ra[i].z, ra[i].w, h1, l1);
            int e = row * PITCH + q * 4;
            *(__nv_bfloat162*)(base + SA_H + e * 2)     = h0;
            *(__nv_bfloat162*)(base + SA_H + e * 2 + 4) = h1;
            *(__nv_bfloat162*)(base + SA_L + e * 2)     = l0;
            *(__nv_bfloat162*)(base + SA_L + e * 2 + 4) = l1;
        }
        #pragma unroll
        for (int p = 0; p < 4; p++) {
            __nv_bfloat162 h, l;
            split_pair(rb[2 * p], rb[2 * p + 1], h, l);
            int e = bn * PITCH + bkh + 2 * p;
            *(__nv_bfloat162*)(base + SB_H + e * 2) = h;
            *(__nv_bfloat162*)(base + SB_L + e * 2) = l;
        }
    };

    ldg_tile(0);
    sts_tile(0);
    __syncthreads();

    for (int t = 0; t < nk; t++) {
        const int buf = t & 1;
        if (t + 1 < nk) ldg_tile(t + 1);

        const char* ahp = smem + buf * BUFSZ + SA_H;
        const char* alp = smem + buf * BUFSZ + SA_L;
        const char* bhp = smem + buf * BUFSZ + SB_H;
        const char* blp = smem + buf * BUFSZ + SB_L;

        #pragma unroll
        for (int ks = 0; ks < 2; ks++) {
            const int acol = ks * 16 + tig * 2;
            uint32_t bh[4][2], bl[4][2];
            #pragma unroll
            for (int an = 0; an < 4; an++) {
                const int brow = wn * 32 + an * 8 + gid;
                const int e = (brow * PITCH + acol) * 2;
                bh[an][0] = *(const uint32_t*)(bhp + e);
                bh[an][1] = *(const uint32_t*)(bhp + e + 16);
                bl[an][0] = *(const uint32_t*)(blp + e);
                bl[an][1] = *(const uint32_t*)(blp + e + 16);
            }
            #pragma unroll
            for (int am = 0; am < 4; am++) {
                const int arow = wm * 64 + am * 16 + gid;
                const int e00 = (arow * PITCH + acol) * 2;
                const int e10 = ((arow + 8) * PITCH + acol) * 2;
                uint32_t ah[4], al[4];
                ah[0] = *(const uint32_t*)(ahp + e00);
                ah[1] = *(const uint32_t*)(ahp + e10);
                ah[2] = *(const uint32_t*)(ahp + e00 + 16);
                ah[3] = *(const uint32_t*)(ahp + e10 + 16);
                al[0] = *(const uint32_t*)(alp + e00);
                al[1] = *(const uint32_t*)(alp + e10);
                al[2] = *(const uint32_t*)(alp + e00 + 16);
                al[3] = *(const uint32_t*)(alp + e10 + 16);
                #pragma unroll
                for (int an = 0; an < 4; an++) {
                    mma16816(c[am][an], ah, bh[an]);
                    mma16816(c[am][an], ah, bl[an]);
                    mma16816(c[am][an], al, bh[an]);
                }
            }
        }

        if (t + 1 < nk) sts_tile(buf ^ 1);
        __syncthreads();
    }

    // ---- epilogue ----
    #pragma unroll
    for (int am = 0; am < 4; am++) {
        #pragma unroll
        for (int an = 0; an < 4; an++) {
            const int col = n0 + wn * 32 + an * 8 + tig * 2;
            float bx = 0.f, by = 0.f;
            if (ACT != 3) { bx = bias[col]; by = bias[col + 1]; }
            #pragma unroll
            for (int hrow = 0; hrow < 2; hrow++) {
                const int m = m0 + wm * 64 + am * 16 + gid + hrow * 8;
                float vx = c[am][an][hrow * 2 + 0] + bx;
                float vy = c[am][an][hrow * 2 + 1] + by;
                if (ACT == 1) { vx = fmaxf(vx, 0.f); vy = fmaxf(vy, 0.f); }
                if (ACT == 2) {
                    vx = vx / (1.f + expf(-vx));
                    vy = vy / (1.f + expf(-vy));
                }
                if (RES) {
                    const float2 r2 = *(const float2*)&R[(long)m * N + col];
                    vx += r2.x; vy += r2.y;
                }
                *(float2*)&Cz[(long)m * N + col] = make_float2(vx, vy);
            }
        }
    }
}

// ---------------- split-K reduce + bias + silu --------------------------------
__global__ void reduce_silu_kernel(const float* __restrict__ part,
                                   const float* __restrict__ bias,
                                   float* __restrict__ out) {
    const long MN = (long)B_ * HEADH_;
    const long i4 = (long)blockIdx.x * 256 + threadIdx.x;
    const long e = i4 * 4;
    const int n = (int)(e % HEADH_);
    float4 a = *(const float4*)&part[e];
    #pragma unroll
    for (int z = 1; z < SPLITK; z++) {
        const float4 p = *(const float4*)&part[z * MN + e];
        a.x += p.x; a.y += p.y; a.z += p.z; a.w += p.w;
    }
    const float4 bi = *(const float4*)&bias[n];
    a.x += bi.x; a.y += bi.y; a.z += bi.z; a.w += bi.w;
    a.x = a.x / (1.f + expf(-a.x));
    a.y = a.y / (1.f + expf(-a.y));
    a.z = a.z / (1.f + expf(-a.z));
    a.w = a.w / (1.f + expf(-a.w));
    *(float4*)&out[e] = a;
}

// ---------------- fused attention per (b,h); out += attn (R7 version) --------
__global__ __launch_bounds__(96)
void attn_kernel(const float* __restrict__ qkv, float* __restrict__ out) {
    const int h = blockIdx.x, b = blockIdx.y;
    __shared__ __align__(16) float Ks[T1_ * 32];
    __shared__ __align__(16) float Vs[T1_ * 32];
    __shared__ float S[T1_ * 67];
    const float* base = qkv + (long)b * T1_ * 768 + h * 96;

    for (int idx = threadIdx.x; idx < T1_ * 8; idx += 96) {
        int r = idx >> 3, c4 = (idx & 7) << 2;
        *(float4*)&Ks[r * 32 + c4] = *(const float4*)&base[r * 768 + 32 + c4];
        *(float4*)&Vs[r * 32 + c4] = *(const float4*)&base[r * 768 + 64 + c4];
    }
    __syncthreads();

    const int r = threadIdx.x;
    if (r < T1_) {
        float4 q4[8];
        #pragma unroll
        for (int j = 0; j < 8; j++)
            q4[j] = *(const float4*)&base[r * 768 + j * 4];

        float mx = -1e30f;
        for (int k = 0; k < T1_; k++) {
            float acc = 0.f;
            #pragma unroll
            for (int j = 0; j < 8; j++) {
                const float4 kv = *(const float4*)&Ks[k * 32 + j * 4];
                acc += q4[j].x * kv.x + q4[j].y * kv.y + q4[j].z * kv.z + q4[j].w * kv.w;
            }
            acc *= 0.17677669529663687f;
            S[r * 67 + k] = acc;
            mx = fmaxf(mx, acc);
        }
        float sum = 0.f;
        for (int k = 0; k < T1_; k++) {
            float e = expf(S[r * 67 + k] - mx);
            S[r * 67 + k] = e;
            sum += e;
        }
        const float inv = 1.f / sum;

        float4 acc4[8];
        #pragma unroll
        for (int j = 0; j < 8; j++) acc4[j] = make_float4(0.f, 0.f, 0.f, 0.f);
        for (int k = 0; k < T1_; k++) {
            const float s = S[r * 67 + k];
            #pragma unroll
            for (int j = 0; j < 8; j++) {
                const float4 vv = *(const float4*)&Vs[k * 32 + j * 4];
                acc4[j].x += s * vv.x; acc4[j].y += s * vv.y;
                acc4[j].z += s * vv.z; acc4[j].w += s * vv.w;
            }
        }
        float* op = out + ((long)b * T1_ + r) * D_ + h * HD_;
        #pragma unroll
        for (int j = 0; j < 8; j++) {
            float4 o = *(float4*)&op[j * 4];
            o.x += acc4[j].x * inv; o.y += acc4[j].y * inv;
            o.z += acc4[j].z * inv; o.w += acc4[j].w * inv;
            *(float4*)&op[j * 4] = o;
        }
    }
}

// ---------------- final classifier head --------------------------------------
__global__ void head2_kernel(const float* __restrict__ hid, const float* __restrict__ W2,
                             const float* __restrict__ b2, float* __restrict__ out) {
    int b = blockIdx.x;
    float acc[NCLS_] = {};
    for (int k = threadIdx.x; k < HEADH_; k += 256) {
        float hv = hid[(long)b * HEADH_ + k];
        #pragma unroll
        for (int c = 0; c < NCLS_; c++) acc[c] += hv * W2[k * NCLS_ + c];
    }
    __shared__ float red[256];
    for (int c = 0; c < NCLS_; c++) {
        red[threadIdx.x] = acc[c];
        __syncthreads();
        for (int o = 128; o > 0; o >>= 1) {
            if (threadIdx.x < o) red[threadIdx.x] += red[threadIdx.x + o];
            __syncthreads();
        }
        if (threadIdx.x == 0) out[b * NCLS_ + c] = red[0] + b2[c];
        __syncthreads();
    }
}

// -----------------------------------------------------------------------------
extern "C" void kernel_launch(void* const* d_in, const int* in_sizes, int n_in,
                              void* d_out, int out_size) {
    const float* x      = (const float*)d_in[0];
    const float* cls    = (const float*)d_in[1];
    const float* Wp     = (const float*)d_in[2];
    const float* bp     = (const float*)d_in[3];
    const float* qkv_w  = (const float*)d_in[4];
    const float* qkv_b  = (const float*)d_in[5];
    const float* ln_w   = (const float*)d_in[6];
    const float* ln_b   = (const float*)d_in[7];
    const float* mlp1_w = (const float*)d_in[8];
    const float* mlp1_b = (const float*)d_in[9];
    const float* mlp2_w = (const float*)d_in[10];
    const float* mlp2_b = (const float*)d_in[11];
    const float* h1w    = (const float*)d_in[12];
    const float* h1b    = (const float*)d_in[13];
    const float* h2w    = (const float*)d_in[14];
    const float* h2b    = (const float*)d_in[15];
    float* out = (float*)d_out;

    float *p_out, *p_h, *p_qkv, *p_m, *p_hid, *p_part;
    cudaGetSymbolAddress((void**)&p_out, g_out);
    cudaGetSymbolAddress((void**)&p_h,   g_h);
    cudaGetSymbolAddress((void**)&p_qkv, g_qkv);
    cudaGetSymbolAddress((void**)&p_m,   g_m);
    cudaGetSymbolAddress((void**)&p_hid, g_hid);
    cudaGetSymbolAddress((void**)&p_part, g_part);

    cudaFuncSetAttribute(gemm_tc<0,false>, cudaFuncAttributeMaxDynamicSharedMemorySize, GSMEM_TOTAL);
    cudaFuncSetAttribute(gemm_tc<1,false>, cudaFuncAttributeMaxDynamicSharedMemorySize, GSMEM_TOTAL);
    cudaFuncSetAttribute(gemm_tc<0,true>,  cudaFuncAttributeMaxDynamicSharedMemorySize, GSMEM_TOTAL);
    cudaFuncSetAttribute(gemm_tc<3,false>, cudaFuncAttributeMaxDynamicSharedMemorySize, GSMEM_TOTAL);

    dim3 gPatch(B_, T1_);
    patch_embed_kernel<<<gPatch, 256>>>(x, cls, Wp, bp, p_out);

    const int Mt = B_ * T1_;   // 16640 rows, /256 = 65 m-tiles
    for (int l = 0; l < 2; l++) {
        ln2d_kernel<<<B_, 256>>>(p_out, ln_w + l * ND_, ln_b + l * ND_, p_h);
        gemm_tc<0, false><<<dim3(768 / 128, Mt / 256), 512, GSMEM_TOTAL>>>(
            p_h, qkv_w + l * D_ * 768, qkv_b + l * 768, nullptr, p_qkv,
            Mt, 768, D_, D_);
        attn_kernel<<<dim3(H_, B_), 96>>>(p_qkv, p_out);
        ln2d_kernel<<<B_, 256>>>(p_out, ln_w + l * ND_, ln_b + l * ND_, p_h);
        gemm_tc<1, false><<<dim3(MLPH_ / 128, Mt / 256), 512, GSMEM_TOTAL>>>(
            p_h, mlp1_w + l * D_ * MLPH_, mlp1_b + l * MLPH_, nullptr, p_m,
            Mt, MLPH_, D_, D_);
        gemm_tc<0, true><<<dim3(D_ / 128, Mt / 256), 512, GSMEM_TOTAL>>>(
            p_m, mlp2_w + l * MLPH_ * D_, mlp2_b + l * D_, p_out, p_out,
            Mt, D_, MLPH_, MLPH_);
    }

    // head1 split-K: partials then fused reduce+bias+silu
    gemm_tc<3, false><<<dim3(HEADH_ / 128, B_ / 256, SPLITK), 512, GSMEM_TOTAL>>>(
        p_out, h1w, h1b, nullptr, p_part, B_, HEADH_, ND_, KCHUNK);
    reduce_silu_kernel<<<(B_ * HEADH_) / 1024, 256>>>(p_part, h1b, p_hid);

    head2_kernel<<<B_, 256>>>(p_hid, h2w, h2b, out);
}